// round 16
// baseline (speedup 1.0000x reference)
#include <cuda_runtime.h>
#include <cuda_fp16.h>
#include <cstdint>

// ---------------------------------------------------------------------------
// HiPPO-LegT full-state scan as parallel GEMMs (subchunk-32 restructure).
// out[t] = A^{u+1} H_S + sum_{j<=u} K_j f[t-j], u = t mod 32, S = t/32.
// Round 14 (= round 12 resubmit after infra failure): k_powers on tensor
// cores via tf32x3 compensated mma; k_main conv tiles skip zero taps.
// ---------------------------------------------------------------------------

#define LSEQ 2048
#define BT   128
#define NST  256
#define CH   128
#define NG   16
#define NSUB 64
#define NPAIR 105
#define MATSZ (NST * NST)

// matrix ids: 0..31 = T[i] = A^{i+1}; 32 = A^64; 33 = A^96; 34+r = P[r]
__device__ float    g_T[34 * MATSZ];
__device__ uint32_t g_Ttf[34 * MATSZ];
__device__ __half   g_Th[32 * MATSZ];
__device__ float    g_P[15 * MATSZ];
__device__ uint32_t g_Ptf[15 * MATSZ];
__device__ float    g_K[32 * NST];
__device__ uint32_t g_Kttf[NST * CH];
__device__ __half   g_Kth[NST * CH];
__device__ float    g_w2[NSUB * BT * NST];
__device__ uint32_t g_w2tf[NSUB * BT * NST];
__device__ float    g_w[NG * BT * NST];
__device__ uint32_t g_wtf[NG * BT * NST];
__device__ float    g_part[NPAIR * BT * NST];
__device__ uint32_t g_h2tf[NSUB * BT * NST];
__device__ __half   g_hh[NSUB * BT * NST];
__device__ int      g_ready[64];

// ============================ helpers ======================================
__device__ __forceinline__ uint32_t smem_u32(const void* p) {
    uint32_t a;
    asm("{ .reg .u64 t; cvta.to.shared.u64 t, %1; cvt.u32.u64 %0, t; }"
        : "=r"(a) : "l"(p));
    return a;
}
__device__ __forceinline__ uint32_t f2tf(float x) {
    uint32_t r;
    asm("cvt.rna.tf32.f32 %0, %1;" : "=r"(r) : "f"(x));
    return r;
}
__device__ __forceinline__ uint32_t f2h2(float lo, float hi) {
    __half2 h = __floats2half2_rn(lo, hi);
    return *(uint32_t*)&h;
}
__device__ __forceinline__ void ldsm4(uint32_t addr, uint32_t& r0, uint32_t& r1,
                                      uint32_t& r2, uint32_t& r3) {
    asm volatile("ldmatrix.sync.aligned.m8n8.x4.shared.b16 {%0,%1,%2,%3}, [%4];"
                 : "=r"(r0), "=r"(r1), "=r"(r2), "=r"(r3) : "r"(addr));
}
__device__ __forceinline__ void mma_tf32(float* c, uint32_t a0, uint32_t a1,
                                         uint32_t a2, uint32_t a3,
                                         uint32_t b0, uint32_t b1) {
    asm volatile(
        "mma.sync.aligned.m16n8k8.row.col.f32.tf32.tf32.f32 "
        "{%0,%1,%2,%3}, {%4,%5,%6,%7}, {%8,%9}, {%0,%1,%2,%3};"
        : "+f"(c[0]), "+f"(c[1]), "+f"(c[2]), "+f"(c[3])
        : "r"(a0), "r"(a1), "r"(a2), "r"(a3), "r"(b0), "r"(b1));
}
__device__ __forceinline__ void mma_f16(float* c, uint32_t a0, uint32_t a1,
                                        uint32_t a2, uint32_t a3,
                                        uint32_t b0, uint32_t b1) {
    asm volatile(
        "mma.sync.aligned.m16n8k16.row.col.f32.f16.f16.f32 "
        "{%0,%1,%2,%3}, {%4,%5,%6,%7}, {%8,%9}, {%0,%1,%2,%3};"
        : "+f"(c[0]), "+f"(c[1]), "+f"(c[2]), "+f"(c[3])
        : "r"(a0), "r"(a1), "r"(a2), "r"(a3), "r"(b0), "r"(b1));
}
#define CP_ASYNC16(dst, src) \
    asm volatile("cp.async.cg.shared.global [%0], [%1], 16;" \
                 :: "r"(dst), "l"(src) : "memory")
#define CP_COMMIT() asm volatile("cp.async.commit_group;" ::: "memory")
#define CP_WAIT1()  asm volatile("cp.async.wait_group 1;" ::: "memory")

// tf32 swizzle: 32 floats (128B) per row
__device__ __forceinline__ uint32_t sw_off(int row, int k) {
    return (uint32_t)(row * 128 + ((((k >> 2) ^ (row & 7)) << 4) | ((k & 3) << 2)));
}
__device__ __forceinline__ void wait_ready(int id) {
    if (id == 0) return;
    int v;
    do {
        asm volatile("ld.acquire.gpu.global.b32 %0, [%1];"
                     : "=r"(v) : "l"(g_ready + id));
        if (v < 4) __nanosleep(100);
    } while (v < 4);
}
__device__ __forceinline__ const float* matp(int id) {
    return (id < 34) ? g_T + (size_t)id * MATSZ : g_P + (size_t)(id - 34) * MATSZ;
}

// ============================ k_init =======================================
__global__ void k_init(const float* __restrict__ A, const float* __restrict__ Bv) {
    int i = blockIdx.x * blockDim.x + threadIdx.x;
    if (i < MATSZ) {
        g_T[i] = A[i];
        g_Ttf[i] = f2tf(A[i]);
        g_Th[i] = __float2half_rn(A[i]);
    }
    if (i < NST) {
        g_K[i] = Bv[i];
        g_Kttf[i * CH] = f2tf(Bv[i]);
        g_Kth[i * CH] = __float2half_rn(Bv[i]);
    }
    if (i < 64) g_ready[i] = 0;
}

// ============================ k_powers (tf32x3 mma) ========================
// 48 products x 4 CTAs (128x128 tile, K=256). Flag-synchronized DAG.
// O = X @ Y with X,Y fp32; each split hi+lo tf32; O ~= Xh Yh + Xh Yl + Xl Yh.
__global__ void __launch_bounds__(256, 1) k_powers_mma() {
    const int p = blockIdx.x >> 2, q = blockIdx.x & 3;
    const int tid = threadIdx.x;

    int xid, yid, oid;
    if (p < 31) {
        int o = p + 1;
        int d = 1 << (31 - __clz(o));
        xid = o - d; yid = d - 1; oid = o;
    } else if (p == 31) { xid = 31; yid = 31; oid = 32; }
    else if (p == 32)   { xid = 32; yid = 31; oid = 33; }
    else if (p == 33)   { xid = 32; yid = 32; oid = 34; }
    else {
        int o = p - 33;
        int d = 1 << (31 - __clz(o));
        xid = 34 + o - d; yid = 34 + d - 1; oid = 34 + o;
    }

    const float* __restrict__ X = matp(xid);
    const float* __restrict__ Y = matp(yid);

    if (tid == 0) {
        wait_ready(xid);
        if (yid != xid) wait_ready(yid);
    }
    __syncthreads();

    const int r0 = (q >> 1) * 128, c0 = (q & 1) * 128;

    __shared__ uint32_t sAh[4096];   // [r][k] hi
    __shared__ uint32_t sAl[4096];   // [r][k] lo
    __shared__ uint32_t sBh[4096];   // [c][k] hi (Y transposed)
    __shared__ uint32_t sBl[4096];   // [c][k] lo
    const uint32_t Ah_u = smem_u32(sAh);
    const uint32_t Al_u = smem_u32(sAl);
    const uint32_t Bh_u = smem_u32(sBh);
    const uint32_t Bl_u = smem_u32(sBl);

    const int lane = tid & 31;
    const int wid = tid >> 5;
    const int wm = wid >> 2, wn = wid & 3;     // 2x4 warps, warp tile 64x32

    float acc[4][4][4];
#pragma unroll
    for (int mi = 0; mi < 4; mi++)
#pragma unroll
        for (int ni = 0; ni < 4; ni++)
#pragma unroll
            for (int qq = 0; qq < 4; qq++) acc[mi][ni][qq] = 0.f;

    const int a_row = wm * 64 + (lane & 7) + ((lane >> 3) & 1) * 8;
    const int a_csel = (lane >> 4) & 1;
    const int b_row = wn * 32 + (lane & 7) + ((lane >> 4) << 3);
    const int b_csel = (lane >> 3) & 1;

    for (int itk = 0; itk < 8; ++itk) {
        int k0 = itk * 32;
        // A tile 128r x 32k, natural
#pragma unroll
        for (int i = 0; i < 4; i++) {
            int e = tid + i * 256;
            int r = e >> 3, kq = (e & 7) << 2;
            float4 v = *(const float4*)&X[(size_t)(r0 + r) * NST + k0 + kq];
            uint4 hi = make_uint4(f2tf(v.x), f2tf(v.y), f2tf(v.z), f2tf(v.w));
            float4 lo = make_float4(v.x - __uint_as_float(hi.x),
                                    v.y - __uint_as_float(hi.y),
                                    v.z - __uint_as_float(hi.z),
                                    v.w - __uint_as_float(hi.w));
            uint32_t off = sw_off(r, kq);
            *(uint4*)((char*)sAh + off) = hi;
            *(uint4*)((char*)sAl + off) =
                make_uint4(f2tf(lo.x), f2tf(lo.y), f2tf(lo.z), f2tf(lo.w));
        }
        // B tile: Y[k][c] transposed into [c][k]
#pragma unroll
        for (int i = 0; i < 4; i++) {
            int e = tid + i * 256;
            int kk = e >> 5, cq = (e & 31) << 2;
            float4 v = *(const float4*)&Y[(size_t)(k0 + kk) * NST + c0 + cq];
            float vv[4] = {v.x, v.y, v.z, v.w};
#pragma unroll
            for (int qz = 0; qz < 4; qz++) {
                uint32_t hi = f2tf(vv[qz]);
                float lo = vv[qz] - __uint_as_float(hi);
                uint32_t off = sw_off(cq + qz, kk);
                *(uint32_t*)((char*)sBh + off) = hi;
                *(uint32_t*)((char*)sBl + off) = f2tf(lo);
            }
        }
        __syncthreads();

#pragma unroll
        for (int pass = 0; pass < 3; pass++) {
            uint32_t Au = (pass == 2) ? Al_u : Ah_u;
            uint32_t Bu = (pass == 1) ? Bl_u : Bh_u;
#pragma unroll
            for (int kt = 0; kt < 4; kt++) {
                uint32_t a[4][4], b[2][4];
#pragma unroll
                for (int mi = 0; mi < 4; mi++) {
                    int r = a_row + mi * 16;
                    int kc = kt * 8 + a_csel * 4;
                    ldsm4(Au + (uint32_t)(r * 128) + ((uint32_t)(((kc >> 2) ^ (r & 7)) << 4)),
                          a[mi][0], a[mi][1], a[mi][2], a[mi][3]);
                }
#pragma unroll
                for (int nb = 0; nb < 2; nb++) {
                    int r = b_row + nb * 16;
                    int kc = kt * 8 + b_csel * 4;
                    ldsm4(Bu + (uint32_t)(r * 128) + ((uint32_t)(((kc >> 2) ^ (r & 7)) << 4)),
                          b[nb][0], b[nb][1], b[nb][2], b[nb][3]);
                }
#pragma unroll
                for (int mi = 0; mi < 4; mi++)
#pragma unroll
                    for (int ni = 0; ni < 4; ni++)
                        mma_tf32(acc[mi][ni], a[mi][0], a[mi][1], a[mi][2], a[mi][3],
                                 b[ni >> 1][(ni & 1) * 2], b[ni >> 1][(ni & 1) * 2 + 1]);
            }
        }
        __syncthreads();
    }

    float* O = (oid < 34) ? g_T + (size_t)oid * MATSZ : g_P + (size_t)(oid - 34) * MATSZ;
    uint32_t* Otf = (oid < 34) ? g_Ttf + (size_t)oid * MATSZ : g_Ptf + (size_t)(oid - 34) * MATSZ;
    const int er = r0 + wm * 64 + (lane >> 2);
    const int ec0 = c0 + wn * 32 + (lane & 3) * 2;
#pragma unroll
    for (int mi = 0; mi < 4; mi++) {
        int rr0 = er + mi * 16;
#pragma unroll
        for (int ni = 0; ni < 4; ni++) {
            int c = ec0 + ni * 8;
#pragma unroll
            for (int half = 0; half < 2; half++) {
                int rr = rr0 + half * 8;
                float v0 = acc[mi][ni][half * 2 + 0];
                float v1 = acc[mi][ni][half * 2 + 1];
                size_t idx = (size_t)rr * NST + c;
                O[idx] = v0; O[idx + 1] = v1;
                Otf[idx] = f2tf(v0); Otf[idx + 1] = f2tf(v1);
                if (oid < 32) {
                    g_Th[(size_t)oid * MATSZ + idx] = __float2half_rn(v0);
                    g_Th[(size_t)oid * MATSZ + idx + 1] = __float2half_rn(v1);
                }
            }
        }
    }
    __syncthreads();
    if (tid == 0) {
        __threadfence();
        atomicAdd(&g_ready[oid], 1);
    }
}

// ============================ k_kern =======================================
__global__ void k_kern(const float* __restrict__ Bv) {
    int j = blockIdx.x + 1;
    const float* __restrict__ T = g_T + (size_t)(j - 1) * MATSZ;
    __shared__ float Bs[NST];
    int tid = threadIdx.x;
    if (tid < NST) Bs[tid] = Bv[tid];
    __syncthreads();
    int warp = tid >> 5, lane = tid & 31;
    for (int n = warp; n < NST; n += 8) {
        float s = 0.f;
        for (int k = lane; k < NST; k += 32) s += T[(size_t)n * NST + k] * Bs[k];
#pragma unroll
        for (int o = 16; o; o >>= 1) s += __shfl_xor_sync(0xFFFFFFFFu, s, o);
        if (!lane) {
            g_K[j * NST + n] = s;
            g_Kttf[n * CH + j] = f2tf(s);
            g_Kth[n * CH + j] = __float2half_rn(s);
        }
    }
}

// ============================ k_w2 (tf32 mma) ==============================
__global__ void __launch_bounds__(256, 1)
k_w2(const float* __restrict__ f) {
    __shared__ uint32_t sA[4096];
    __shared__ uint32_t sB[4096];
    const uint32_t As_u = smem_u32(sA);
    const uint32_t Bs_u = smem_u32(sB);

    const int S = blockIdx.y;
    const int n0 = blockIdx.x * 128;
    const int tid = threadIdx.x;
    const int lane = tid & 31;
    const int wid = tid >> 5;
    const int wm = wid >> 2, wn = wid & 3;

    float acc[4][4][4];
#pragma unroll
    for (int mi = 0; mi < 4; mi++)
#pragma unroll
        for (int ni = 0; ni < 4; ni++)
#pragma unroll
            for (int qq = 0; qq < 4; qq++) acc[mi][ni][qq] = 0.f;

    const int a_row = wm * 64 + (lane & 7) + ((lane >> 3) & 1) * 8;
    const int a_csel = (lane >> 4) & 1;
    const int b_row = wn * 32 + (lane & 7) + ((lane >> 4) << 3);
    const int b_csel = (lane >> 3) & 1;

#pragma unroll
    for (int i = 0; i < 16; i++) {
        int e = tid + i * 256;
        int b = e & 127, j = e >> 7;
        *(uint32_t*)((char*)sA + sw_off(b, j)) =
            f2tf(f[(size_t)(32 * S + 31 - j) * BT + b]);
    }
#pragma unroll
    for (int i = 0; i < 4; i++) {
        int e = tid + i * 256;
        int r = e >> 3, kq = (e & 7) << 2;
        *(uint4*)((char*)sB + sw_off(r, kq)) =
            *(const uint4*)&g_Kttf[(size_t)(n0 + r) * CH + kq];
    }
    __syncthreads();
#pragma unroll
    for (int kt = 0; kt < 4; kt++) {
        uint32_t a[4][4], b[2][4];
#pragma unroll
        for (int mi = 0; mi < 4; mi++) {
            int r = a_row + mi * 16;
            int kc = kt * 8 + a_csel * 4;
            ldsm4(As_u + (uint32_t)(r * 128) + ((uint32_t)(((kc >> 2) ^ (r & 7)) << 4)),
                  a[mi][0], a[mi][1], a[mi][2], a[mi][3]);
        }
#pragma unroll
        for (int nb = 0; nb < 2; nb++) {
            int r = b_row + nb * 16;
            int kc = kt * 8 + b_csel * 4;
            ldsm4(Bs_u + (uint32_t)(r * 128) + ((uint32_t)(((kc >> 2) ^ (r & 7)) << 4)),
                  b[nb][0], b[nb][1], b[nb][2], b[nb][3]);
        }
#pragma unroll
        for (int mi = 0; mi < 4; mi++)
#pragma unroll
            for (int ni = 0; ni < 4; ni++)
                mma_tf32(acc[mi][ni], a[mi][0], a[mi][1], a[mi][2], a[mi][3],
                         b[ni >> 1][(ni & 1) * 2], b[ni >> 1][(ni & 1) * 2 + 1]);
    }

    const int er = wm * 64 + (lane >> 2);
    const int ec0 = wn * 32 + (lane & 3) * 2;
#pragma unroll
    for (int mi = 0; mi < 4; mi++) {
        int r0 = er + mi * 16;
#pragma unroll
        for (int ni = 0; ni < 4; ni++) {
            int c = ec0 + ni * 8;
            size_t i0 = ((size_t)S * BT + r0) * NST + n0 + c;
            size_t i1 = ((size_t)S * BT + r0 + 8) * NST + n0 + c;
            g_w2[i0] = acc[mi][ni][0]; g_w2[i0 + 1] = acc[mi][ni][1];
            g_w2[i1] = acc[mi][ni][2]; g_w2[i1 + 1] = acc[mi][ni][3];
            g_w2tf[i0] = f2tf(acc[mi][ni][0]); g_w2tf[i0 + 1] = f2tf(acc[mi][ni][1]);
            g_w2tf[i1] = f2tf(acc[mi][ni][2]); g_w2tf[i1 + 1] = f2tf(acc[mi][ni][3]);
        }
    }
}

// ============================ k_wg (tf32 mma) ==============================
__global__ void __launch_bounds__(256, 1)
k_wg() {
    __shared__ uint32_t sA[4096];
    __shared__ uint32_t sB[4096];
    const uint32_t As_u = smem_u32(sA);
    const uint32_t Bs_u = smem_u32(sB);

    const int g = blockIdx.y;
    const int n0 = blockIdx.x * 128;
    const int tid = threadIdx.x;
    const int lane = tid & 31;
    const int wid = tid >> 5;
    const int wm = wid >> 2, wn = wid & 3;

    float acc[4][4][4];
#pragma unroll
    for (int mi = 0; mi < 4; mi++)
#pragma unroll
        for (int ni = 0; ni < 4; ni++)
#pragma unroll
            for (int qq = 0; qq < 4; qq++) acc[mi][ni][qq] = 0.f;

    const int a_row = wm * 64 + (lane & 7) + ((lane >> 3) & 1) * 8;
    const int a_csel = (lane >> 4) & 1;
    const int b_row = wn * 32 + (lane & 7) + ((lane >> 4) << 3);
    const int b_csel = (lane >> 3) & 1;

    const int matid[3] = {33, 32, 31};
    for (int pass = 0; pass < 3; ++pass) {
        const uint32_t* __restrict__ W = g_w2tf + (size_t)(4 * g + pass) * BT * NST;
        const uint32_t* __restrict__ Bm = g_Ttf + (size_t)matid[pass] * MATSZ;
        for (int it = 0; it < 8; ++it) {
            int k0 = it * 32;
#pragma unroll
            for (int i = 0; i < 4; i++) {
                int e = tid + i * 256;
                int r = e >> 3, kq = (e & 7) << 2;
                *(uint4*)((char*)sA + sw_off(r, kq)) =
                    *(const uint4*)&W[(size_t)r * NST + k0 + kq];
            }
#pragma unroll
            for (int i = 0; i < 4; i++) {
                int e = tid + i * 256;
                int r = e >> 3, kq = (e & 7) << 2;
                *(uint4*)((char*)sB + sw_off(r, kq)) =
                    *(const uint4*)&Bm[(size_t)(n0 + r) * NST + k0 + kq];
            }
            __syncthreads();
#pragma unroll
            for (int kt = 0; kt < 4; kt++) {
                uint32_t a[4][4], b[2][4];
#pragma unroll
                for (int mi = 0; mi < 4; mi++) {
                    int r = a_row + mi * 16;
                    int kc = kt * 8 + a_csel * 4;
                    ldsm4(As_u + (uint32_t)(r * 128) + ((uint32_t)(((kc >> 2) ^ (r & 7)) << 4)),
                          a[mi][0], a[mi][1], a[mi][2], a[mi][3]);
                }
#pragma unroll
                for (int nb = 0; nb < 2; nb++) {
                    int r = b_row + nb * 16;
                    int kc = kt * 8 + b_csel * 4;
                    ldsm4(Bs_u + (uint32_t)(r * 128) + ((uint32_t)(((kc >> 2) ^ (r & 7)) << 4)),
                          b[nb][0], b[nb][1], b[nb][2], b[nb][3]);
                }
#pragma unroll
                for (int mi = 0; mi < 4; mi++)
#pragma unroll
                    for (int ni = 0; ni < 4; ni++)
                        mma_tf32(acc[mi][ni], a[mi][0], a[mi][1], a[mi][2], a[mi][3],
                                 b[ni >> 1][(ni & 1) * 2], b[ni >> 1][(ni & 1) * 2 + 1]);
            }
            __syncthreads();
        }
    }

    const float* __restrict__ Wlast = g_w2 + (size_t)(4 * g + 3) * BT * NST;
    const int er = wm * 64 + (lane >> 2);
    const int ec0 = wn * 32 + (lane & 3) * 2;
#pragma unroll
    for (int mi = 0; mi < 4; mi++) {
        int r0 = er + mi * 16;
#pragma unroll
        for (int ni = 0; ni < 4; ni++) {
            int c = ec0 + ni * 8;
            size_t l0 = (size_t)r0 * NST + n0 + c;
            size_t l1 = (size_t)(r0 + 8) * NST + n0 + c;
            float v00 = acc[mi][ni][0] + Wlast[l0];
            float v01 = acc[mi][ni][1] + Wlast[l0 + 1];
            float v10 = acc[mi][ni][2] + Wlast[l1];
            float v11 = acc[mi][ni][3] + Wlast[l1 + 1];
            size_t i0 = (size_t)g * BT * NST + l0;
            size_t i1 = (size_t)g * BT * NST + l1;
            g_w[i0] = v00; g_w[i0 + 1] = v01;
            g_w[i1] = v10; g_w[i1 + 1] = v11;
            g_wtf[i0] = f2tf(v00); g_wtf[i0 + 1] = f2tf(v01);
            g_wtf[i1] = f2tf(v10); g_wtf[i1 + 1] = f2tf(v11);
        }
    }
}

// ============================ k_h1 (tf32 mma) ==============================
__global__ void __launch_bounds__(256, 1)
k_h1_mma() {
    extern __shared__ char smem[];
    const uint32_t As_u = smem_u32(smem);
    const uint32_t Bs_u = As_u + 16384;

    int z = blockIdx.x;
    int zr = z, g = 2;
    while (zr >= g - 1) { zr -= g - 1; g++; }
    int m = zr;
    int lag = g - 2 - m;

    const uint32_t* __restrict__ W = g_wtf + (size_t)m * BT * NST;
    const uint32_t* __restrict__ P = g_Ptf + (size_t)lag * MATSZ;
    float* __restrict__ OUT = g_part + (size_t)z * BT * NST;

    const int tid = threadIdx.x;
    const int lane = tid & 31;
    const int wid = tid >> 5;
    const int wm = wid >> 2, wn = wid & 3;

    float acc[4][8][4];
#pragma unroll
    for (int mi = 0; mi < 4; mi++)
#pragma unroll
        for (int ni = 0; ni < 8; ni++)
#pragma unroll
            for (int qq = 0; qq < 4; qq++) acc[mi][ni][qq] = 0.f;

    const int a_row = wm * 64 + (lane & 7) + ((lane >> 3) & 1) * 8;
    const int a_csel = (lane >> 4) & 1;
    const int b_row = wn * 64 + (lane & 7) + ((lane >> 4) << 3);
    const int b_csel = (lane >> 3) & 1;

    for (int it = 0; it < 8; ++it) {
        int k0 = it * 32;
#pragma unroll
        for (int i = 0; i < 4; i++) {
            int e = tid + i * 256;
            int r = e >> 3, kq = (e & 7) << 2;
            *(uint4*)(smem + sw_off(r, kq)) = *(const uint4*)&W[(size_t)r * NST + k0 + kq];
        }
#pragma unroll
        for (int i = 0; i < 8; i++) {
            int e = tid + i * 256;
            int r = e >> 3, kq = (e & 7) << 2;
            *(uint4*)(smem + 16384 + sw_off(r, kq)) = *(const uint4*)&P[(size_t)r * NST + k0 + kq];
        }
        __syncthreads();
#pragma unroll
        for (int kt = 0; kt < 4; kt++) {
            uint32_t a[4][4], b[4][4];
#pragma unroll
            for (int mi = 0; mi < 4; mi++) {
                int r = a_row + mi * 16;
                int kc = kt * 8 + a_csel * 4;
                ldsm4(As_u + (uint32_t)(r * 128) + ((uint32_t)(((kc >> 2) ^ (r & 7)) << 4)),
                      a[mi][0], a[mi][1], a[mi][2], a[mi][3]);
            }
#pragma unroll
            for (int nb = 0; nb < 4; nb++) {
                int r = b_row + nb * 16;
                int kc = kt * 8 + b_csel * 4;
                ldsm4(Bs_u + (uint32_t)(r * 128) + ((uint32_t)(((kc >> 2) ^ (r & 7)) << 4)),
                      b[nb][0], b[nb][1], b[nb][2], b[nb][3]);
            }
#pragma unroll
            for (int mi = 0; mi < 4; mi++)
#pragma unroll
                for (int ni = 0; ni < 8; ni++)
                    mma_tf32(acc[mi][ni], a[mi][0], a[mi][1], a[mi][2], a[mi][3],
                             b[ni >> 1][(ni & 1) * 2], b[ni >> 1][(ni & 1) * 2 + 1]);
        }
        __syncthreads();
    }

    const int er = wm * 64 + (lane >> 2);
    const int ec0 = wn * 64 + (lane & 3) * 2;
#pragma unroll
    for (int mi = 0; mi < 4; mi++) {
        int r0 = er + mi * 16;
#pragma unroll
        for (int ni = 0; ni < 8; ni++) {
            int c = ec0 + ni * 8;
            *(float2*)&OUT[(size_t)r0 * NST + c] =
                make_float2(acc[mi][ni][0], acc[mi][ni][1]);
            *(float2*)&OUT[(size_t)(r0 + 8) * NST + c] =
                make_float2(acc[mi][ni][2], acc[mi][ni][3]);
        }
    }
}

// ============================ k_h2 =========================================
__global__ void k_h2() {
    int i = blockIdx.x * blockDim.x + threadIdx.x;
    if (i >= NG * BT * NST) return;
    int g = i / (BT * NST);
    int r = i % (BT * NST);
    float v = 0.f;
    if (g >= 1) v = g_w[(size_t)(g - 1) * BT * NST + r];
    if (g >= 2) {
        int base = (g - 1) * (g - 2) / 2;
        for (int m = 0; m <= g - 2; m++)
            v += g_part[(size_t)(base + m) * BT * NST + r];
    }
    size_t o = (size_t)(4 * g) * BT * NST + r;
    g_h2tf[o] = f2tf(v);
    g_hh[o] = __float2half_rn(v);
}

// ============================ k_hsub (tf32 mma) ============================
__global__ void __launch_bounds__(256, 1)
k_hsub(int s) {
    __shared__ uint32_t sA[4096];
    __shared__ uint32_t sB[4096];
    const uint32_t As_u = smem_u32(sA);
    const uint32_t Bs_u = smem_u32(sB);

    const int g = blockIdx.y;
    const int n0 = blockIdx.x * 128;
    const int Sp = 4 * g + s - 1;
    const int So = Sp + 1;
    const int tid = threadIdx.x;
    const int lane = tid & 31;
    const int wid = tid >> 5;
    const int wm = wid >> 2, wn = wid & 3;

    const uint32_t* __restrict__ Hp = g_h2tf + (size_t)Sp * BT * NST;
    const uint32_t* __restrict__ Bm = g_Ttf + (size_t)31 * MATSZ;

    float acc[4][4][4];
#pragma unroll
    for (int mi = 0; mi < 4; mi++)
#pragma unroll
        for (int ni = 0; ni < 4; ni++)
#pragma unroll
            for (int qq = 0; qq < 4; qq++) acc[mi][ni][qq] = 0.f;

    const int a_row = wm * 64 + (lane & 7) + ((lane >> 3) & 1) * 8;
    const int a_csel = (lane >> 4) & 1;
    const int b_row = wn * 32 + (lane & 7) + ((lane >> 4) << 3);
    const int b_csel = (lane >> 3) & 1;

    for (int it = 0; it < 8; ++it) {
        int k0 = it * 32;
#pragma unroll
        for (int i = 0; i < 4; i++) {
            int e = tid + i * 256;
            int r = e >> 3, kq = (e & 7) << 2;
            *(uint4*)((char*)sA + sw_off(r, kq)) =
                *(const uint4*)&Hp[(size_t)r * NST + k0 + kq];
        }
#pragma unroll
        for (int i = 0; i < 4; i++) {
            int e = tid + i * 256;
            int r = e >> 3, kq = (e & 7) << 2;
            *(uint4*)((char*)sB + sw_off(r, kq)) =
                *(const uint4*)&Bm[(size_t)(n0 + r) * NST + k0 + kq];
        }
        __syncthreads();
#pragma unroll
        for (int kt = 0; kt < 4; kt++) {
            uint32_t a[4][4], b[2][4];
#pragma unroll
            for (int mi = 0; mi < 4; mi++) {
                int r = a_row + mi * 16;
                int kc = kt * 8 + a_csel * 4;
                ldsm4(As_u + (uint32_t)(r * 128) + ((uint32_t)(((kc >> 2) ^ (r & 7)) << 4)),
                      a[mi][0], a[mi][1], a[mi][2], a[mi][3]);
            }
#pragma unroll
            for (int nb = 0; nb < 2; nb++) {
                int r = b_row + nb * 16;
                int kc = kt * 8 + b_csel * 4;
                ldsm4(Bs_u + (uint32_t)(r * 128) + ((uint32_t)(((kc >> 2) ^ (r & 7)) << 4)),
                      b[nb][0], b[nb][1], b[nb][2], b[nb][3]);
            }
#pragma unroll
            for (int mi = 0; mi < 4; mi++)
#pragma unroll
                for (int ni = 0; ni < 4; ni++)
                    mma_tf32(acc[mi][ni], a[mi][0], a[mi][1], a[mi][2], a[mi][3],
                             b[ni >> 1][(ni & 1) * 2], b[ni >> 1][(ni & 1) * 2 + 1]);
        }
        __syncthreads();
    }

    const float* __restrict__ W2 = g_w2 + (size_t)Sp * BT * NST;
    const int er = wm * 64 + (lane >> 2);
    const int ec0 = wn * 32 + (lane & 3) * 2;
#pragma unroll
    for (int mi = 0; mi < 4; mi++) {
        int r0 = er + mi * 16;
#pragma unroll
        for (int ni = 0; ni < 4; ni++) {
            int c = ec0 + ni * 8;
            size_t l0 = (size_t)r0 * NST + n0 + c;
            size_t l1 = (size_t)(r0 + 8) * NST + n0 + c;
            float v00 = acc[mi][ni][0] + W2[l0];
            float v01 = acc[mi][ni][1] + W2[l0 + 1];
            float v10 = acc[mi][ni][2] + W2[l1];
            float v11 = acc[mi][ni][3] + W2[l1 + 1];
            size_t o0 = (size_t)So * BT * NST + l0;
            size_t o1 = (size_t)So * BT * NST + l1;
            g_h2tf[o0] = f2tf(v00); g_h2tf[o0 + 1] = f2tf(v01);
            g_h2tf[o1] = f2tf(v10); g_h2tf[o1 + 1] = f2tf(v11);
            g_hh[o0] = __float2half_rn(v00); g_hh[o0 + 1] = __float2half_rn(v01);
            g_hh[o1] = __float2half_rn(v10); g_hh[o1 + 1] = __float2half_rn(v11);
        }
    }
}

// ============================ k_main (fp16, 128thr, 2 CTA/SM) ==============
#define STG_BYTES 32768
#define SMEM_MAIN (3 * STG_BYTES)

__device__ __forceinline__ uint32_t sw_h(int row, int chunk) {
    return (uint32_t)(row * 128 + ((chunk ^ (row & 7)) << 4));
}

__global__ void __launch_bounds__(128, 2)
k_main_mma(const float* __restrict__ f, float* __restrict__ out) {
    extern __shared__ char smem[];
    const uint32_t s0 = smem_u32(smem);

    const int tid = threadIdx.x;
    const int lane = tid & 31;
    const int wid = tid >> 5;
    const int wm = wid >> 1;
    const int wn = wid & 1;

    const int t = blockIdx.y;
    const int n0 = blockIdx.x * 128;
    const int S = t >> 5, u = t & 31;
    const int p1t = (S > 0) ? 4 : 0;
    const int nT = p1t + 1;
    const int conv_kts = (u >> 4) + 1;   // 1 or 2 valid k16 steps in conv tile

    const __half* __restrict__ Hh = g_hh + (size_t)S * BT * NST;
    const __half* __restrict__ Th = g_Th + (size_t)u * MATSZ;

    float acc[4][8][4];
#pragma unroll
    for (int mi = 0; mi < 4; mi++)
#pragma unroll
        for (int ni = 0; ni < 8; ni++)
#pragma unroll
            for (int qq = 0; qq < 4; qq++) acc[mi][ni][qq] = 0.f;

    const int a_r16 = lane & 15;
    const int a_kc = (lane >> 4) & 1;
    const int b_rb = (lane & 7) + ((lane >> 4) & 1) * 8;
    const int b_kc = (lane >> 3) & 1;

    auto prefetch = [&](int it) {
        if (it < nT) {
            int s = it - (it / 3) * 3;
            uint32_t Au = s0 + (uint32_t)(s * STG_BYTES);
            uint32_t Bu = Au + 16384;
            if (it < p1t) {
                int k0 = it * 64;
#pragma unroll
                for (int i = 0; i < 8; i++) {
                    int e = tid + i * 128;
                    int r = e >> 3, c = e & 7;
                    CP_ASYNC16(Au + sw_h(r, c), Hh + (size_t)r * NST + k0 + c * 8);
                }
#pragma unroll
                for (int i = 0; i < 8; i++) {
                    int e = tid + i * 128;
                    int r = e >> 3, c = e & 7;
                    CP_ASYNC16(Bu + sw_h(r, c),
                               Th + (size_t)(n0 + r) * NST + k0 + c * 8);
                }
            } else {
#pragma unroll
                for (int i = 0; i < 8; i++) {
                    int e = tid + i * 128;
                    int r = e >> 3, c = e & 7;
                    CP_ASYNC16(Bu + sw_h(r, c),
                               g_Kth + (size_t)(n0 + r) * CH + c * 8);
                }
                // only chunks jg<4 (taps j<32) are ever consumed (kt<2)
#pragma unroll
                for (int i = 0; i < 4; i++) {
                    int e = tid + i * 128;
                    int b = e & 127, jg = e >> 7;
                    uint32_t w[4];
#pragma unroll
                    for (int p2 = 0; p2 < 4; p2++) {
                        int ja = jg * 8 + p2 * 2;
                        float v0 = (ja     <= u) ? f[(size_t)(t - ja) * BT + b] : 0.f;
                        float v1 = (ja + 1 <= u) ? f[(size_t)(t - ja - 1) * BT + b] : 0.f;
                        w[p2] = f2h2(v0, v1);
                    }
                    *(uint4*)(smem + s * STG_BYTES + sw_h(b, jg)) =
                        make_uint4(w[0], w[1], w[2], w[3]);
                }
            }
        }
        CP_COMMIT();
    };

    prefetch(0);
    prefetch(1);
    for (int it = 0; it < nT; ++it) {
        CP_WAIT1();
        __syncthreads();

        int s = it - (it / 3) * 3;
        uint32_t Au = s0 + (uint32_t)(s * STG_BYTES);
        uint32_t Bu = Au + 16384;
        const int ktmax = (it == p1t) ? conv_kts : 4;
#pragma unroll 4
        for (int kt = 0; kt < ktmax; kt++) {
            uint32_t a[4][4], b[4][4];
#pragma unroll
            for (int mi = 0; mi < 4; mi++) {
                int r = wm * 64 + mi * 16 + a_r16;
                int c = kt * 2 + a_kc;
                ldsm4(Au + sw_h(r, c), a[mi][0], a[mi][1], a[mi][2], a[mi][3]);
            }
#pragma unroll
            for (int nbp = 0; nbp < 4; nbp++) {
                int r = wn * 64 + nbp * 16 + b_rb;
                int c = kt * 2 + b_kc;
                ldsm4(Bu + sw_h(r, c), b[nbp][0], b[nbp][1], b[nbp][2], b[nbp][3]);
            }
#pragma unroll
            for (int mi = 0; mi < 4; mi++)
#pragma unroll
                for (int n8 = 0; n8 < 8; n8++)
                    mma_f16(acc[mi][n8], a[mi][0], a[mi][1], a[mi][2], a[mi][3],
                            b[n8 >> 1][(n8 & 1) * 2], b[n8 >> 1][(n8 & 1) * 2 + 1]);
        }
        prefetch(it + 2);
    }

    float* __restrict__ o = out + (size_t)t * BT * NST + n0;
    const int er = wm * 64 + (lane >> 2);
    const int ec0 = wn * 64 + (lane & 3) * 2;
#pragma unroll
    for (int mi = 0; mi < 4; mi++) {
        int r0 = er + mi * 16;
#pragma unroll
        for (int n8 = 0; n8 < 8; n8++) {
            int c = ec0 + n8 * 8;
            *(float2*)&o[(size_t)r0 * NST + c] =
                make_float2(acc[mi][n8][0], acc[mi][n8][1]);
            *(float2*)&o[(size_t)(r0 + 8) * NST + c] =
                make_float2(acc[mi][n8][2], acc[mi][n8][3]);
        }
    }
}

// ---------------------------------------------------------------------------
extern "C" void kernel_launch(void* const* d_in, const int* in_sizes, int n_in,
                              void* d_out, int out_size) {
    const float* f = nullptr;
    const float* A = nullptr;
    const float* Bv = nullptr;
    for (int i = 0; i < n_in; i++) {
        if (in_sizes[i] == LSEQ * BT) f = (const float*)d_in[i];
        else if (in_sizes[i] == NST * NST) A = (const float*)d_in[i];
        else if (in_sizes[i] == NST) Bv = (const float*)d_in[i];
    }
    float* out = (float*)d_out;

    cudaFuncSetAttribute(k_main_mma, cudaFuncAttributeMaxDynamicSharedMemorySize,
                         SMEM_MAIN);
    cudaFuncSetAttribute(k_h1_mma, cudaFuncAttributeMaxDynamicSharedMemorySize,
                         49152);

    k_init<<<256, 256>>>(A, Bv);
    k_powers_mma<<<48 * 4, 256>>>();
    k_kern<<<31, 256>>>(Bv);
    k_w2<<<dim3(2, NSUB), 256>>>(f);
    k_wg<<<dim3(2, NG), 256>>>();
    k_h1_mma<<<NPAIR, 256, 49152>>>();
    k_h2<<<(NG * BT * NST + 255) / 256, 256>>>();
    k_hsub<<<dim3(2, NG), 256>>>(1);
    k_hsub<<<dim3(2, NG), 256>>>(2);
    k_hsub<<<dim3(2, NG), 256>>>(3);
    k_main_mma<<<dim3(2, LSEQ), 128, SMEM_MAIN>>>(f, out);
    (void)out_size;
}

// round 17
// speedup vs baseline: 1.8047x; 1.8047x over previous
#include <cuda_runtime.h>
#include <cuda_fp16.h>
#include <cstdint>

// ---------------------------------------------------------------------------
// HiPPO-LegT full-state scan as parallel GEMMs (subchunk-32 restructure).
// out[t] = A^{u+1} H_S + sum_{j<=u} K_j f[t-j], u = t mod 32, S = t/32.
// Round 17: revert to round-11 (431us best: SIMT many-small-CTA powers,
// 128-thread 2CTA/SM k_main) + ONLY conv early-exit in k_main (exact):
// conv tile runs kt=0 (+kt=1 iff u>=16), staging halved to chunks 0-3.
// ---------------------------------------------------------------------------

#define LSEQ 2048
#define BT   128
#define NST  256
#define CH   128
#define NG   16
#define NSUB 64
#define NPAIR 105
#define MATSZ (NST * NST)

// matrix ids: 0..31 = T[i] = A^{i+1}; 32 = A^64; 33 = A^96; 34+r = P[r]
__device__ float    g_T[34 * MATSZ];
__device__ uint32_t g_Ttf[34 * MATSZ];
__device__ __half   g_Th[32 * MATSZ];
__device__ float    g_P[15 * MATSZ];
__device__ uint32_t g_Ptf[15 * MATSZ];
__device__ float    g_K[32 * NST];
__device__ uint32_t g_Kttf[NST * CH];
__device__ __half   g_Kth[NST * CH];
__device__ float    g_w2[NSUB * BT * NST];
__device__ uint32_t g_w2tf[NSUB * BT * NST];
__device__ float    g_w[NG * BT * NST];
__device__ uint32_t g_wtf[NG * BT * NST];
__device__ float    g_part[NPAIR * BT * NST];
__device__ uint32_t g_h2tf[NSUB * BT * NST];
__device__ __half   g_hh[NSUB * BT * NST];
__device__ int      g_ready[64];

// ============================ helpers ======================================
__device__ __forceinline__ uint32_t smem_u32(const void* p) {
    uint32_t a;
    asm("{ .reg .u64 t; cvta.to.shared.u64 t, %1; cvt.u32.u64 %0, t; }"
        : "=r"(a) : "l"(p));
    return a;
}
__device__ __forceinline__ uint32_t f2tf(float x) {
    uint32_t r;
    asm("cvt.rna.tf32.f32 %0, %1;" : "=r"(r) : "f"(x));
    return r;
}
__device__ __forceinline__ uint32_t f2h2(float lo, float hi) {
    __half2 h = __floats2half2_rn(lo, hi);
    return *(uint32_t*)&h;
}
__device__ __forceinline__ void ldsm4(uint32_t addr, uint32_t& r0, uint32_t& r1,
                                      uint32_t& r2, uint32_t& r3) {
    asm volatile("ldmatrix.sync.aligned.m8n8.x4.shared.b16 {%0,%1,%2,%3}, [%4];"
                 : "=r"(r0), "=r"(r1), "=r"(r2), "=r"(r3) : "r"(addr));
}
__device__ __forceinline__ void mma_tf32(float* c, uint32_t a0, uint32_t a1,
                                         uint32_t a2, uint32_t a3,
                                         uint32_t b0, uint32_t b1) {
    asm volatile(
        "mma.sync.aligned.m16n8k8.row.col.f32.tf32.tf32.f32 "
        "{%0,%1,%2,%3}, {%4,%5,%6,%7}, {%8,%9}, {%0,%1,%2,%3};"
        : "+f"(c[0]), "+f"(c[1]), "+f"(c[2]), "+f"(c[3])
        : "r"(a0), "r"(a1), "r"(a2), "r"(a3), "r"(b0), "r"(b1));
}
__device__ __forceinline__ void mma_f16(float* c, uint32_t a0, uint32_t a1,
                                        uint32_t a2, uint32_t a3,
                                        uint32_t b0, uint32_t b1) {
    asm volatile(
        "mma.sync.aligned.m16n8k16.row.col.f32.f16.f16.f32 "
        "{%0,%1,%2,%3}, {%4,%5,%6,%7}, {%8,%9}, {%0,%1,%2,%3};"
        : "+f"(c[0]), "+f"(c[1]), "+f"(c[2]), "+f"(c[3])
        : "r"(a0), "r"(a1), "r"(a2), "r"(a3), "r"(b0), "r"(b1));
}
#define CP_ASYNC16(dst, src) \
    asm volatile("cp.async.cg.shared.global [%0], [%1], 16;" \
                 :: "r"(dst), "l"(src) : "memory")
#define CP_COMMIT() asm volatile("cp.async.commit_group;" ::: "memory")
#define CP_WAIT1()  asm volatile("cp.async.wait_group 1;" ::: "memory")

// tf32 swizzle: 32 floats (128B) per row
__device__ __forceinline__ uint32_t sw_off(int row, int k) {
    return (uint32_t)(row * 128 + ((((k >> 2) ^ (row & 7)) << 4) | ((k & 3) << 2)));
}
__device__ __forceinline__ void wait_ready(int id) {
    if (id == 0) return;
    int v;
    do {
        asm volatile("ld.acquire.gpu.global.b32 %0, [%1];"
                     : "=r"(v) : "l"(g_ready + id));
        if (v < 32) __nanosleep(100);
    } while (v < 32);
}
__device__ __forceinline__ const float* matp(int id) {
    return (id < 34) ? g_T + (size_t)id * MATSZ : g_P + (size_t)(id - 34) * MATSZ;
}

// ============================ k_init =======================================
__global__ void k_init(const float* __restrict__ A, const float* __restrict__ Bv) {
    int i = blockIdx.x * blockDim.x + threadIdx.x;
    if (i < MATSZ) {
        g_T[i] = A[i];
        g_Ttf[i] = f2tf(A[i]);
        g_Th[i] = __float2half_rn(A[i]);
    }
    if (i < NST) {
        g_K[i] = Bv[i];
        g_Kttf[i * CH] = f2tf(Bv[i]);
        g_Kth[i * CH] = __float2half_rn(Bv[i]);
    }
    if (i < 64) g_ready[i] = 0;
}

// ============================ k_powers (SIMT, 32 CTAs/product) =============
__global__ void __launch_bounds__(128) k_powers() {
    const int p = blockIdx.x >> 5, q = blockIdx.x & 31;
    const int tid = threadIdx.x;

    int xid, yid, oid;
    if (p < 31) {
        int o = p + 1;
        int d = 1 << (31 - __clz(o));
        xid = o - d; yid = d - 1; oid = o;
    } else if (p == 31) { xid = 31; yid = 31; oid = 32; }
    else if (p == 32)   { xid = 32; yid = 31; oid = 33; }
    else if (p == 33)   { xid = 32; yid = 32; oid = 34; }
    else {
        int o = p - 33;
        int d = 1 << (31 - __clz(o));
        xid = 34 + o - d; yid = 34 + d - 1; oid = 34 + o;
    }

    const float* __restrict__ X = matp(xid);
    const float* __restrict__ Y = matp(yid);

    if (tid == 0) {
        wait_ready(xid);
        if (yid != xid) wait_ready(yid);
    }
    __syncthreads();

    const int r0 = (q >> 2) * 32, c0 = (q & 3) * 64;
    __shared__ float Xs[16][36];
    __shared__ float Ys[16][68];
    const int tx = tid & 15, ty = tid >> 4;
    float acc[4][4];
#pragma unroll
    for (int i = 0; i < 4; i++)
#pragma unroll
        for (int j = 0; j < 4; j++) acc[i][j] = 0.f;

    for (int k0 = 0; k0 < NST; k0 += 16) {
        {
            int row = tid >> 2, kb = (tid & 3) * 4;
            float4 v = *(const float4*)&X[(size_t)(r0 + row) * NST + k0 + kb];
            Xs[kb + 0][row] = v.x; Xs[kb + 1][row] = v.y;
            Xs[kb + 2][row] = v.z; Xs[kb + 3][row] = v.w;
        }
        {
            int kk = tid >> 3, cb = (tid & 7) * 8;
            *(float4*)&Ys[kk][cb]     = *(const float4*)&Y[(size_t)(k0 + kk) * NST + c0 + cb];
            *(float4*)&Ys[kk][cb + 4] = *(const float4*)&Y[(size_t)(k0 + kk) * NST + c0 + cb + 4];
        }
        __syncthreads();
#pragma unroll
        for (int kk = 0; kk < 16; kk++) {
            float a[4], b[4];
            *(float4*)a = *(const float4*)&Xs[kk][ty * 4];
            *(float4*)b = *(const float4*)&Ys[kk][tx * 4];
#pragma unroll
            for (int i = 0; i < 4; i++)
#pragma unroll
                for (int j = 0; j < 4; j++) acc[i][j] += a[i] * b[j];
        }
        __syncthreads();
    }

    float* O = (oid < 34) ? g_T + (size_t)oid * MATSZ : g_P + (size_t)(oid - 34) * MATSZ;
    uint32_t* Otf = (oid < 34) ? g_Ttf + (size_t)oid * MATSZ : g_Ptf + (size_t)(oid - 34) * MATSZ;
#pragma unroll
    for (int i = 0; i < 4; i++) {
        size_t idx = (size_t)(r0 + ty * 4 + i) * NST + c0 + tx * 4;
        float4 v = make_float4(acc[i][0], acc[i][1], acc[i][2], acc[i][3]);
        *(float4*)&O[idx] = v;
        *(uint4*)&Otf[idx] = make_uint4(f2tf(v.x), f2tf(v.y), f2tf(v.z), f2tf(v.w));
        if (oid < 32) {
            uint2 hv = make_uint2(f2h2(v.x, v.y), f2h2(v.z, v.w));
            *(uint2*)&g_Th[(size_t)oid * MATSZ + idx] = hv;
        }
    }
    __syncthreads();
    if (tid == 0) {
        __threadfence();
        atomicAdd(&g_ready[oid], 1);
    }
}

// ============================ k_kern =======================================
__global__ void k_kern(const float* __restrict__ Bv) {
    int j = blockIdx.x + 1;
    const float* __restrict__ T = g_T + (size_t)(j - 1) * MATSZ;
    __shared__ float Bs[NST];
    int tid = threadIdx.x;
    if (tid < NST) Bs[tid] = Bv[tid];
    __syncthreads();
    int warp = tid >> 5, lane = tid & 31;
    for (int n = warp; n < NST; n += 8) {
        float s = 0.f;
        for (int k = lane; k < NST; k += 32) s += T[(size_t)n * NST + k] * Bs[k];
#pragma unroll
        for (int o = 16; o; o >>= 1) s += __shfl_xor_sync(0xFFFFFFFFu, s, o);
        if (!lane) {
            g_K[j * NST + n] = s;
            g_Kttf[n * CH + j] = f2tf(s);
            g_Kth[n * CH + j] = __float2half_rn(s);
        }
    }
}

// ============================ k_w2 (tf32 mma) ==============================
__global__ void __launch_bounds__(256, 1)
k_w2(const float* __restrict__ f) {
    __shared__ uint32_t sA[4096];
    __shared__ uint32_t sB[4096];
    const uint32_t As_u = smem_u32(sA);
    const uint32_t Bs_u = smem_u32(sB);

    const int S = blockIdx.y;
    const int n0 = blockIdx.x * 128;
    const int tid = threadIdx.x;
    const int lane = tid & 31;
    const int wid = tid >> 5;
    const int wm = wid >> 2, wn = wid & 3;

    float acc[4][4][4];
#pragma unroll
    for (int mi = 0; mi < 4; mi++)
#pragma unroll
        for (int ni = 0; ni < 4; ni++)
#pragma unroll
            for (int qq = 0; qq < 4; qq++) acc[mi][ni][qq] = 0.f;

    const int a_row = wm * 64 + (lane & 7) + ((lane >> 3) & 1) * 8;
    const int a_csel = (lane >> 4) & 1;
    const int b_row = wn * 32 + (lane & 7) + ((lane >> 4) << 3);
    const int b_csel = (lane >> 3) & 1;

#pragma unroll
    for (int i = 0; i < 16; i++) {
        int e = tid + i * 256;
        int b = e & 127, j = e >> 7;
        *(uint32_t*)((char*)sA + sw_off(b, j)) =
            f2tf(f[(size_t)(32 * S + 31 - j) * BT + b]);
    }
#pragma unroll
    for (int i = 0; i < 4; i++) {
        int e = tid + i * 256;
        int r = e >> 3, kq = (e & 7) << 2;
        *(uint4*)((char*)sB + sw_off(r, kq)) =
            *(const uint4*)&g_Kttf[(size_t)(n0 + r) * CH + kq];
    }
    __syncthreads();
#pragma unroll
    for (int kt = 0; kt < 4; kt++) {
        uint32_t a[4][4], b[2][4];
#pragma unroll
        for (int mi = 0; mi < 4; mi++) {
            int r = a_row + mi * 16;
            int kc = kt * 8 + a_csel * 4;
            ldsm4(As_u + (uint32_t)(r * 128) + ((uint32_t)(((kc >> 2) ^ (r & 7)) << 4)),
                  a[mi][0], a[mi][1], a[mi][2], a[mi][3]);
        }
#pragma unroll
        for (int nb = 0; nb < 2; nb++) {
            int r = b_row + nb * 16;
            int kc = kt * 8 + b_csel * 4;
            ldsm4(Bs_u + (uint32_t)(r * 128) + ((uint32_t)(((kc >> 2) ^ (r & 7)) << 4)),
                  b[nb][0], b[nb][1], b[nb][2], b[nb][3]);
        }
#pragma unroll
        for (int mi = 0; mi < 4; mi++)
#pragma unroll
            for (int ni = 0; ni < 4; ni++)
                mma_tf32(acc[mi][ni], a[mi][0], a[mi][1], a[mi][2], a[mi][3],
                         b[ni >> 1][(ni & 1) * 2], b[ni >> 1][(ni & 1) * 2 + 1]);
    }

    const int er = wm * 64 + (lane >> 2);
    const int ec0 = wn * 32 + (lane & 3) * 2;
#pragma unroll
    for (int mi = 0; mi < 4; mi++) {
        int r0 = er + mi * 16;
#pragma unroll
        for (int ni = 0; ni < 4; ni++) {
            int c = ec0 + ni * 8;
            size_t i0 = ((size_t)S * BT + r0) * NST + n0 + c;
            size_t i1 = ((size_t)S * BT + r0 + 8) * NST + n0 + c;
            g_w2[i0] = acc[mi][ni][0]; g_w2[i0 + 1] = acc[mi][ni][1];
            g_w2[i1] = acc[mi][ni][2]; g_w2[i1 + 1] = acc[mi][ni][3];
            g_w2tf[i0] = f2tf(acc[mi][ni][0]); g_w2tf[i0 + 1] = f2tf(acc[mi][ni][1]);
            g_w2tf[i1] = f2tf(acc[mi][ni][2]); g_w2tf[i1 + 1] = f2tf(acc[mi][ni][3]);
        }
    }
}

// ============================ k_wg (tf32 mma) ==============================
__global__ void __launch_bounds__(256, 1)
k_wg() {
    __shared__ uint32_t sA[4096];
    __shared__ uint32_t sB[4096];
    const uint32_t As_u = smem_u32(sA);
    const uint32_t Bs_u = smem_u32(sB);

    const int g = blockIdx.y;
    const int n0 = blockIdx.x * 128;
    const int tid = threadIdx.x;
    const int lane = tid & 31;
    const int wid = tid >> 5;
    const int wm = wid >> 2, wn = wid & 3;

    float acc[4][4][4];
#pragma unroll
    for (int mi = 0; mi < 4; mi++)
#pragma unroll
        for (int ni = 0; ni < 4; ni++)
#pragma unroll
            for (int qq = 0; qq < 4; qq++) acc[mi][ni][qq] = 0.f;

    const int a_row = wm * 64 + (lane & 7) + ((lane >> 3) & 1) * 8;
    const int a_csel = (lane >> 4) & 1;
    const int b_row = wn * 32 + (lane & 7) + ((lane >> 4) << 3);
    const int b_csel = (lane >> 3) & 1;

    const int matid[3] = {33, 32, 31};
    for (int pass = 0; pass < 3; ++pass) {
        const uint32_t* __restrict__ W = g_w2tf + (size_t)(4 * g + pass) * BT * NST;
        const uint32_t* __restrict__ Bm = g_Ttf + (size_t)matid[pass] * MATSZ;
        for (int it = 0; it < 8; ++it) {
            int k0 = it * 32;
#pragma unroll
            for (int i = 0; i < 4; i++) {
                int e = tid + i * 256;
                int r = e >> 3, kq = (e & 7) << 2;
                *(uint4*)((char*)sA + sw_off(r, kq)) =
                    *(const uint4*)&W[(size_t)r * NST + k0 + kq];
            }
#pragma unroll
            for (int i = 0; i < 4; i++) {
                int e = tid + i * 256;
                int r = e >> 3, kq = (e & 7) << 2;
                *(uint4*)((char*)sB + sw_off(r, kq)) =
                    *(const uint4*)&Bm[(size_t)(n0 + r) * NST + k0 + kq];
            }
            __syncthreads();
#pragma unroll
            for (int kt = 0; kt < 4; kt++) {
                uint32_t a[4][4], b[2][4];
#pragma unroll
                for (int mi = 0; mi < 4; mi++) {
                    int r = a_row + mi * 16;
                    int kc = kt * 8 + a_csel * 4;
                    ldsm4(As_u + (uint32_t)(r * 128) + ((uint32_t)(((kc >> 2) ^ (r & 7)) << 4)),
                          a[mi][0], a[mi][1], a[mi][2], a[mi][3]);
                }
#pragma unroll
                for (int nb = 0; nb < 2; nb++) {
                    int r = b_row + nb * 16;
                    int kc = kt * 8 + b_csel * 4;
                    ldsm4(Bs_u + (uint32_t)(r * 128) + ((uint32_t)(((kc >> 2) ^ (r & 7)) << 4)),
                          b[nb][0], b[nb][1], b[nb][2], b[nb][3]);
                }
#pragma unroll
                for (int mi = 0; mi < 4; mi++)
#pragma unroll
                    for (int ni = 0; ni < 4; ni++)
                        mma_tf32(acc[mi][ni], a[mi][0], a[mi][1], a[mi][2], a[mi][3],
                                 b[ni >> 1][(ni & 1) * 2], b[ni >> 1][(ni & 1) * 2 + 1]);
            }
            __syncthreads();
        }
    }

    const float* __restrict__ Wlast = g_w2 + (size_t)(4 * g + 3) * BT * NST;
    const int er = wm * 64 + (lane >> 2);
    const int ec0 = wn * 32 + (lane & 3) * 2;
#pragma unroll
    for (int mi = 0; mi < 4; mi++) {
        int r0 = er + mi * 16;
#pragma unroll
        for (int ni = 0; ni < 4; ni++) {
            int c = ec0 + ni * 8;
            size_t l0 = (size_t)r0 * NST + n0 + c;
            size_t l1 = (size_t)(r0 + 8) * NST + n0 + c;
            float v00 = acc[mi][ni][0] + Wlast[l0];
            float v01 = acc[mi][ni][1] + Wlast[l0 + 1];
            float v10 = acc[mi][ni][2] + Wlast[l1];
            float v11 = acc[mi][ni][3] + Wlast[l1 + 1];
            size_t i0 = (size_t)g * BT * NST + l0;
            size_t i1 = (size_t)g * BT * NST + l1;
            g_w[i0] = v00; g_w[i0 + 1] = v01;
            g_w[i1] = v10; g_w[i1 + 1] = v11;
            g_wtf[i0] = f2tf(v00); g_wtf[i0 + 1] = f2tf(v01);
            g_wtf[i1] = f2tf(v10); g_wtf[i1 + 1] = f2tf(v11);
        }
    }
}

// ============================ k_h1 (tf32 mma) ==============================
__global__ void __launch_bounds__(256, 1)
k_h1_mma() {
    extern __shared__ char smem[];
    const uint32_t As_u = smem_u32(smem);
    const uint32_t Bs_u = As_u + 16384;

    int z = blockIdx.x;
    int zr = z, g = 2;
    while (zr >= g - 1) { zr -= g - 1; g++; }
    int m = zr;
    int lag = g - 2 - m;

    const uint32_t* __restrict__ W = g_wtf + (size_t)m * BT * NST;
    const uint32_t* __restrict__ P = g_Ptf + (size_t)lag * MATSZ;
    float* __restrict__ OUT = g_part + (size_t)z * BT * NST;

    const int tid = threadIdx.x;
    const int lane = tid & 31;
    const int wid = tid >> 5;
    const int wm = wid >> 2, wn = wid & 3;

    float acc[4][8][4];
#pragma unroll
    for (int mi = 0; mi < 4; mi++)
#pragma unroll
        for (int ni = 0; ni < 8; ni++)
#pragma unroll
            for (int qq = 0; qq < 4; qq++) acc[mi][ni][qq] = 0.f;

    const int a_row = wm * 64 + (lane & 7) + ((lane >> 3) & 1) * 8;
    const int a_csel = (lane >> 4) & 1;
    const int b_row = wn * 64 + (lane & 7) + ((lane >> 4) << 3);
    const int b_csel = (lane >> 3) & 1;

    for (int it = 0; it < 8; ++it) {
        int k0 = it * 32;
#pragma unroll
        for (int i = 0; i < 4; i++) {
            int e = tid + i * 256;
            int r = e >> 3, kq = (e & 7) << 2;
            *(uint4*)(smem + sw_off(r, kq)) = *(const uint4*)&W[(size_t)r * NST + k0 + kq];
        }
#pragma unroll
        for (int i = 0; i < 8; i++) {
            int e = tid + i * 256;
            int r = e >> 3, kq = (e & 7) << 2;
            *(uint4*)(smem + 16384 + sw_off(r, kq)) = *(const uint4*)&P[(size_t)r * NST + k0 + kq];
        }
        __syncthreads();
#pragma unroll
        for (int kt = 0; kt < 4; kt++) {
            uint32_t a[4][4], b[4][4];
#pragma unroll
            for (int mi = 0; mi < 4; mi++) {
                int r = a_row + mi * 16;
                int kc = kt * 8 + a_csel * 4;
                ldsm4(As_u + (uint32_t)(r * 128) + ((uint32_t)(((kc >> 2) ^ (r & 7)) << 4)),
                      a[mi][0], a[mi][1], a[mi][2], a[mi][3]);
            }
#pragma unroll
            for (int nb = 0; nb < 4; nb++) {
                int r = b_row + nb * 16;
                int kc = kt * 8 + b_csel * 4;
                ldsm4(Bs_u + (uint32_t)(r * 128) + ((uint32_t)(((kc >> 2) ^ (r & 7)) << 4)),
                      b[nb][0], b[nb][1], b[nb][2], b[nb][3]);
            }
#pragma unroll
            for (int mi = 0; mi < 4; mi++)
#pragma unroll
                for (int ni = 0; ni < 8; ni++)
                    mma_tf32(acc[mi][ni], a[mi][0], a[mi][1], a[mi][2], a[mi][3],
                             b[ni >> 1][(ni & 1) * 2], b[ni >> 1][(ni & 1) * 2 + 1]);
        }
        __syncthreads();
    }

    const int er = wm * 64 + (lane >> 2);
    const int ec0 = wn * 64 + (lane & 3) * 2;
#pragma unroll
    for (int mi = 0; mi < 4; mi++) {
        int r0 = er + mi * 16;
#pragma unroll
        for (int ni = 0; ni < 8; ni++) {
            int c = ec0 + ni * 8;
            *(float2*)&OUT[(size_t)r0 * NST + c] =
                make_float2(acc[mi][ni][0], acc[mi][ni][1]);
            *(float2*)&OUT[(size_t)(r0 + 8) * NST + c] =
                make_float2(acc[mi][ni][2], acc[mi][ni][3]);
        }
    }
}

// ============================ k_h2 =========================================
__global__ void k_h2() {
    int i = blockIdx.x * blockDim.x + threadIdx.x;
    if (i >= NG * BT * NST) return;
    int g = i / (BT * NST);
    int r = i % (BT * NST);
    float v = 0.f;
    if (g >= 1) v = g_w[(size_t)(g - 1) * BT * NST + r];
    if (g >= 2) {
        int base = (g - 1) * (g - 2) / 2;
        for (int m = 0; m <= g - 2; m++)
            v += g_part[(size_t)(base + m) * BT * NST + r];
    }
    size_t o = (size_t)(4 * g) * BT * NST + r;
    g_h2tf[o] = f2tf(v);
    g_hh[o] = __float2half_rn(v);
}

// ============================ k_hsub (tf32 mma) ============================
__global__ void __launch_bounds__(256, 1)
k_hsub(int s) {
    __shared__ uint32_t sA[4096];
    __shared__ uint32_t sB[4096];
    const uint32_t As_u = smem_u32(sA);
    const uint32_t Bs_u = smem_u32(sB);

    const int g = blockIdx.y;
    const int n0 = blockIdx.x * 128;
    const int Sp = 4 * g + s - 1;
    const int So = Sp + 1;
    const int tid = threadIdx.x;
    const int lane = tid & 31;
    const int wid = tid >> 5;
    const int wm = wid >> 2, wn = wid & 3;

    const uint32_t* __restrict__ Hp = g_h2tf + (size_t)Sp * BT * NST;
    const uint32_t* __restrict__ Bm = g_Ttf + (size_t)31 * MATSZ;

    float acc[4][4][4];
#pragma unroll
    for (int mi = 0; mi < 4; mi++)
#pragma unroll
        for (int ni = 0; ni < 4; ni++)
#pragma unroll
            for (int qq = 0; qq < 4; qq++) acc[mi][ni][qq] = 0.f;

    const int a_row = wm * 64 + (lane & 7) + ((lane >> 3) & 1) * 8;
    const int a_csel = (lane >> 4) & 1;
    const int b_row = wn * 32 + (lane & 7) + ((lane >> 4) << 3);
    const int b_csel = (lane >> 3) & 1;

    for (int it = 0; it < 8; ++it) {
        int k0 = it * 32;
#pragma unroll
        for (int i = 0; i < 4; i++) {
            int e = tid + i * 256;
            int r = e >> 3, kq = (e & 7) << 2;
            *(uint4*)((char*)sA + sw_off(r, kq)) =
                *(const uint4*)&Hp[(size_t)r * NST + k0 + kq];
        }
#pragma unroll
        for (int i = 0; i < 4; i++) {
            int e = tid + i * 256;
            int r = e >> 3, kq = (e & 7) << 2;
            *(uint4*)((char*)sB + sw_off(r, kq)) =
                *(const uint4*)&Bm[(size_t)(n0 + r) * NST + k0 + kq];
        }
        __syncthreads();
#pragma unroll
        for (int kt = 0; kt < 4; kt++) {
            uint32_t a[4][4], b[2][4];
#pragma unroll
            for (int mi = 0; mi < 4; mi++) {
                int r = a_row + mi * 16;
                int kc = kt * 8 + a_csel * 4;
                ldsm4(As_u + (uint32_t)(r * 128) + ((uint32_t)(((kc >> 2) ^ (r & 7)) << 4)),
                      a[mi][0], a[mi][1], a[mi][2], a[mi][3]);
            }
#pragma unroll
            for (int nb = 0; nb < 2; nb++) {
                int r = b_row + nb * 16;
                int kc = kt * 8 + b_csel * 4;
                ldsm4(Bs_u + (uint32_t)(r * 128) + ((uint32_t)(((kc >> 2) ^ (r & 7)) << 4)),
                      b[nb][0], b[nb][1], b[nb][2], b[nb][3]);
            }
#pragma unroll
            for (int mi = 0; mi < 4; mi++)
#pragma unroll
                for (int ni = 0; ni < 4; ni++)
                    mma_tf32(acc[mi][ni], a[mi][0], a[mi][1], a[mi][2], a[mi][3],
                             b[ni >> 1][(ni & 1) * 2], b[ni >> 1][(ni & 1) * 2 + 1]);
        }
        __syncthreads();
    }

    const float* __restrict__ W2 = g_w2 + (size_t)Sp * BT * NST;
    const int er = wm * 64 + (lane >> 2);
    const int ec0 = wn * 32 + (lane & 3) * 2;
#pragma unroll
    for (int mi = 0; mi < 4; mi++) {
        int r0 = er + mi * 16;
#pragma unroll
        for (int ni = 0; ni < 4; ni++) {
            int c = ec0 + ni * 8;
            size_t l0 = (size_t)r0 * NST + n0 + c;
            size_t l1 = (size_t)(r0 + 8) * NST + n0 + c;
            float v00 = acc[mi][ni][0] + W2[l0];
            float v01 = acc[mi][ni][1] + W2[l0 + 1];
            float v10 = acc[mi][ni][2] + W2[l1];
            float v11 = acc[mi][ni][3] + W2[l1 + 1];
            size_t o0 = (size_t)So * BT * NST + l0;
            size_t o1 = (size_t)So * BT * NST + l1;
            g_h2tf[o0] = f2tf(v00); g_h2tf[o0 + 1] = f2tf(v01);
            g_h2tf[o1] = f2tf(v10); g_h2tf[o1 + 1] = f2tf(v11);
            g_hh[o0] = __float2half_rn(v00); g_hh[o0 + 1] = __float2half_rn(v01);
            g_hh[o1] = __float2half_rn(v10); g_hh[o1 + 1] = __float2half_rn(v11);
        }
    }
}

// ============================ k_main (fp16, 128thr, 2 CTA/SM) ==============
// grid (2, LSEQ). 4 warps 2x2, warp tile 64x64, 3-stage 32KB ring.
// Conv tile early-exit: only taps j<=u<=31 exist -> kt=0 (+kt=1 iff u>=16);
// conv staging fills only chunks 0..3 (the only ones consumed).
#define STG_BYTES 32768
#define SMEM_MAIN (3 * STG_BYTES)

__device__ __forceinline__ uint32_t sw_h(int row, int chunk) {
    return (uint32_t)(row * 128 + ((chunk ^ (row & 7)) << 4));
}

__global__ void __launch_bounds__(128, 2)
k_main_mma(const float* __restrict__ f, float* __restrict__ out) {
    extern __shared__ char smem[];
    const uint32_t s0 = smem_u32(smem);

    const int tid = threadIdx.x;
    const int lane = tid & 31;
    const int wid = tid >> 5;
    const int wm = wid >> 1;
    const int wn = wid & 1;

    const int t = blockIdx.y;
    const int n0 = blockIdx.x * 128;
    const int S = t >> 5, u = t & 31;
    const int p1t = (S > 0) ? 4 : 0;
    const int nT = p1t + 1;

    const __half* __restrict__ Hh = g_hh + (size_t)S * BT * NST;
    const __half* __restrict__ Th = g_Th + (size_t)u * MATSZ;

    float acc[4][8][4];
#pragma unroll
    for (int mi = 0; mi < 4; mi++)
#pragma unroll
        for (int ni = 0; ni < 8; ni++)
#pragma unroll
            for (int qq = 0; qq < 4; qq++) acc[mi][ni][qq] = 0.f;

    const int a_r16 = lane & 15;
    const int a_kc = (lane >> 4) & 1;
    const int b_rb = (lane & 7) + ((lane >> 4) & 1) * 8;
    const int b_kc = (lane >> 3) & 1;

    auto prefetch = [&](int it) {
        if (it < nT) {
            int s = it - (it / 3) * 3;
            uint32_t Au = s0 + (uint32_t)(s * STG_BYTES);
            uint32_t Bu = Au + 16384;
            if (it < p1t) {
                int k0 = it * 64;
#pragma unroll
                for (int i = 0; i < 8; i++) {
                    int e = tid + i * 128;
                    int r = e >> 3, c = e & 7;
                    CP_ASYNC16(Au + sw_h(r, c), Hh + (size_t)r * NST + k0 + c * 8);
                }
#pragma unroll
                for (int i = 0; i < 8; i++) {
                    int e = tid + i * 128;
                    int r = e >> 3, c = e & 7;
                    CP_ASYNC16(Bu + sw_h(r, c),
                               Th + (size_t)(n0 + r) * NST + k0 + c * 8);
                }
            } else {
                // conv tile: only chunks c<4 (taps j<32) are ever consumed
#pragma unroll
                for (int i = 0; i < 4; i++) {
                    int e = tid + i * 128;
                    int r = e >> 2, c = e & 3;
                    CP_ASYNC16(Bu + sw_h(r, c),
                               g_Kth + (size_t)(n0 + r) * CH + c * 8);
                }
#pragma unroll
                for (int i = 0; i < 4; i++) {
                    int e = tid + i * 128;
                    int b = e & 127, jg = (e >> 7) & 3;   // jg 0..3
                    uint32_t w[4];
#pragma unroll
                    for (int p2 = 0; p2 < 4; p2++) {
                        int ja = jg * 8 + p2 * 2;
                        float v0 = (ja     <= u) ? f[(size_t)(t - ja) * BT + b] : 0.f;
                        float v1 = (ja + 1 <= u) ? f[(size_t)(t - ja - 1) * BT + b] : 0.f;
                        w[p2] = f2h2(v0, v1);
                    }
                    *(uint4*)(smem + s * STG_BYTES + sw_h(b, jg)) =
                        make_uint4(w[0], w[1], w[2], w[3]);
                }
            }
        }
        CP_COMMIT();
    };

    // one kt step (k16) against stage buffers
    auto do_kt = [&](int kt, uint32_t Au, uint32_t Bu) {
        uint32_t a[4][4], b[4][4];
#pragma unroll
        for (int mi = 0; mi < 4; mi++) {
            int r = wm * 64 + mi * 16 + a_r16;
            int c = kt * 2 + a_kc;
            ldsm4(Au + sw_h(r, c), a[mi][0], a[mi][1], a[mi][2], a[mi][3]);
        }
#pragma unroll
        for (int nbp = 0; nbp < 4; nbp++) {
            int r = wn * 64 + nbp * 16 + b_rb;
            int c = kt * 2 + b_kc;
            ldsm4(Bu + sw_h(r, c), b[nbp][0], b[nbp][1], b[nbp][2], b[nbp][3]);
        }
#pragma unroll
        for (int mi = 0; mi < 4; mi++)
#pragma unroll
            for (int n8 = 0; n8 < 8; n8++)
                mma_f16(acc[mi][n8], a[mi][0], a[mi][1], a[mi][2], a[mi][3],
                        b[n8 >> 1][(n8 & 1) * 2], b[n8 >> 1][(n8 & 1) * 2 + 1]);
    };

    prefetch(0);
    prefetch(1);
    for (int it = 0; it < nT; ++it) {
        CP_WAIT1();
        __syncthreads();

        int s = it - (it / 3) * 3;
        uint32_t Au = s0 + (uint32_t)(s * STG_BYTES);
        uint32_t Bu = Au + 16384;
        if (it < p1t) {
            do_kt(0, Au, Bu);
            do_kt(1, Au, Bu);
            do_kt(2, Au, Bu);
            do_kt(3, Au, Bu);
        } else {
            do_kt(0, Au, Bu);
            if (u >= 16) do_kt(1, Au, Bu);
        }
        prefetch(it + 2);
    }

    float* __restrict__ o = out + (size_t)t * BT * NST + n0;
    const int er = wm * 64 + (lane >> 2);
    const int ec0 = wn * 64 + (lane & 3) * 2;
#pragma unroll
    for (int mi = 0; mi < 4; mi++) {
        int r0 = er + mi * 16;
#pragma unroll
        for (int n8 = 0; n8 < 8; n8++) {
            int c = ec0 + n8 * 8;
            *(float2*)&o[(size_t)r0 * NST + c] =
                make_float2(acc[mi][n8][0], acc[mi][n8][1]);
            *(float2*)&o[(size_t)(r0 + 8) * NST + c] =
                make_float2(acc[mi][n8][2], acc[mi][n8][3]);
        }
    }
}

// ---------------------------------------------------------------------------
extern "C" void kernel_launch(void* const* d_in, const int* in_sizes, int n_in,
                              void* d_out, int out_size) {
    const float* f = nullptr;
    const float* A = nullptr;
    const float* Bv = nullptr;
    for (int i = 0; i < n_in; i++) {
        if (in_sizes[i] == LSEQ * BT) f = (const float*)d_in[i];
        else if (in_sizes[i] == NST * NST) A = (const float*)d_in[i];
        else if (in_sizes[i] == NST) Bv = (const float*)d_in[i];
    }
    float* out = (float*)d_out;

    cudaFuncSetAttribute(k_main_mma, cudaFuncAttributeMaxDynamicSharedMemorySize,
                         SMEM_MAIN);
    cudaFuncSetAttribute(k_h1_mma, cudaFuncAttributeMaxDynamicSharedMemorySize,
                         49152);

    k_init<<<256, 256>>>(A, Bv);
    k_powers<<<48 * 32, 128>>>();
    k_kern<<<31, 256>>>(Bv);
    k_w2<<<dim3(2, NSUB), 256>>>(f);
    k_wg<<<dim3(2, NG), 256>>>();
    k_h1_mma<<<NPAIR, 256, 49152>>>();
    k_h2<<<(NG * BT * NST + 255) / 256, 256>>>();
    k_hsub<<<dim3(2, NG), 256>>>(1);
    k_hsub<<<dim3(2, NG), 256>>>(2);
    k_hsub<<<dim3(2, NG), 256>>>(3);
    k_main_mma<<<dim3(2, LSEQ), 128, SMEM_MAIN>>>(f, out);
    (void)out_size;
}